// round 8
// baseline (speedup 1.0000x reference)
#include <cuda_runtime.h>
#include <math.h>

#define F_CNT 1024
#define HH 192
#define WW 192
#define NPIX (HH*WW)
#define FXc 200.0f
#define FYc 200.0f
#define CXc 96.0f
#define CYc 96.0f
#define EPSf 1e-8f
#define SEG 8
#define GSEG 128                   // F_CNT / SEG
#define NRBLK 288                  // render blocks: each owns 2 x 64-px row-runs

// ---------------- device scratch (no allocations allowed) ----------------
__device__ float4 g_sh1[F_CNT];    // sorted: mx, my, pA(=-.5*conA), pB(=-conB)
__device__ float  g_spC[F_CNT];    // sorted: pC(=-.5*conC)
__device__ float4 g_scold[F_CNT];  // sorted: opv, r, g, b
__device__ float  g_partial[NRBLK];
__device__ int    g_count;         // 0-init; ticket counter, reset by last block

// ================= preprocess + stable sort, one block =================
__global__ void __launch_bounds__(1024) prep_sort_kernel(
        const float* __restrict__ vp,
        const int*   __restrict__ faces,
        const float* __restrict__ qs,
        const float* __restrict__ ls,
        const float* __restrict__ cols,
        const float* __restrict__ lop)
{
    __shared__ float4 h1s[F_CNT];
    __shared__ float  pCs[F_CNT];
    __shared__ float4 colds[F_CNT];
    __shared__ unsigned long long sk[F_CNT];

    int f = threadIdx.x;

    int ia = faces[3*f+0], ib = faces[3*f+1], ic = faces[3*f+2];
    float ax = vp[3*ia], ay = vp[3*ia+1], az = vp[3*ia+2];
    float bx = vp[3*ib], by = vp[3*ib+1], bz = vp[3*ib+2];
    float cx = vp[3*ic], cy = vp[3*ic+1], cz = vp[3*ic+2];

    float tx = (ax+bx+cx)/3.0f, ty = (ay+by+cy)/3.0f, tz = (az+bz+cz)/3.0f;

    float e1x = bx-ax, e1y = by-ay, e1z = bz-az;
    float e2x = cx-ax, e2y = cy-ay, e2z = cz-az;
    float l1 = sqrtf(e1x*e1x + e1y*e1y + e1z*e1z);
    float i1 = 1.0f/(l1 + EPSf);
    float xx = e1x*i1, xy = e1y*i1, xz = e1z*i1;
    float nx = e1y*e2z - e1z*e2y;
    float ny = e1z*e2x - e1x*e2z;
    float nz = e1x*e2y - e1y*e2x;
    float ln = sqrtf(nx*nx + ny*ny + nz*nz);
    float in = 1.0f/(ln + EPSf);
    float zx = nx*in, zy = ny*in, zz = nz*in;
    float yx = zy*xz - zz*xy;
    float yy = zz*xx - zx*xz;
    float yz = zx*xy - zy*xx;

    float qw = qs[4*f+0], qx = qs[4*f+1], qy = qs[4*f+2], qz = qs[4*f+3];
    float qn = sqrtf(qw*qw + qx*qx + qy*qy + qz*qz);
    float iq = 1.0f/(qn + EPSf);
    qw *= iq; qx *= iq; qy *= iq; qz *= iq;
    float R00 = 1.0f - 2.0f*(qy*qy + qz*qz), R01 = 2.0f*(qx*qy - qw*qz), R02 = 2.0f*(qx*qz + qw*qy);
    float R10 = 2.0f*(qx*qy + qw*qz), R11 = 1.0f - 2.0f*(qx*qx + qz*qz), R12 = 2.0f*(qy*qz - qw*qx);
    float R20 = 2.0f*(qx*qz - qw*qy), R21 = 2.0f*(qy*qz + qw*qx), R22 = 1.0f - 2.0f*(qx*qx + qy*qy);

    float s0 = expf(ls[3*f+0]), s1 = expf(ls[3*f+1]), s2 = expf(ls[3*f+2]);

    float G[3][3];
    {
        float w0, w1, w2;
        w0 = R00*s0; w1 = R01*s1; w2 = R02*s2;
        G[0][0] = xx*w0 + yx*w1 + zx*w2;
        G[1][0] = xy*w0 + yy*w1 + zy*w2;
        G[2][0] = xz*w0 + yz*w1 + zz*w2;
        w0 = R10*s0; w1 = R11*s1; w2 = R12*s2;
        G[0][1] = xx*w0 + yx*w1 + zx*w2;
        G[1][1] = xy*w0 + yy*w1 + zy*w2;
        G[2][1] = xz*w0 + yz*w1 + zz*w2;
        w0 = R20*s0; w1 = R21*s1; w2 = R22*s2;
        G[0][2] = xx*w0 + yx*w1 + zx*w2;
        G[1][2] = xy*w0 + yy*w1 + zy*w2;
        G[2][2] = xz*w0 + yz*w1 + zz*w2;
    }

    float gs[3], Gr[3][3];
    #pragma unroll
    for (int j = 0; j < 3; j++) {
        gs[j] = sqrtf(G[0][j]*G[0][j] + G[1][j]*G[1][j] + G[2][j]*G[2][j]);
        float ig = 1.0f/(gs[j] + EPSf);
        Gr[0][j] = G[0][j]*ig; Gr[1][j] = G[1][j]*ig; Gr[2][j] = G[2][j]*ig;
    }

    float m00 = Gr[0][0], m11 = Gr[1][1], m22 = Gr[2][2];
    float pw = 0.5f*sqrtf(fmaxf(EPSf, 1.0f + m00 + m11 + m22));
    float px = 0.5f*sqrtf(fmaxf(EPSf, 1.0f + m00 - m11 - m22));
    float py = 0.5f*sqrtf(fmaxf(EPSf, 1.0f - m00 + m11 - m22));
    float pz = 0.5f*sqrtf(fmaxf(EPSf, 1.0f - m00 - m11 + m22));
    px = copysignf(px, Gr[2][1] - Gr[1][2]);
    py = copysignf(py, Gr[0][2] - Gr[2][0]);
    pz = copysignf(pz, Gr[1][0] - Gr[0][1]);

    float pn = sqrtf(pw*pw + px*px + py*py + pz*pz);
    float ip = 1.0f/(pn + EPSf);
    pw *= ip; px *= ip; py *= ip; pz *= ip;
    float N00 = 1.0f - 2.0f*(py*py + pz*pz), N01 = 2.0f*(px*py - pw*pz), N02 = 2.0f*(px*pz + pw*py);
    float N10 = 2.0f*(px*py + pw*pz), N11 = 1.0f - 2.0f*(px*px + pz*pz), N12 = 2.0f*(py*pz - pw*px);
    float N20 = 2.0f*(px*pz - pw*py), N21 = 2.0f*(py*pz + pw*px), N22 = 1.0f - 2.0f*(px*px + py*py);

    float M00 = N00*gs[0], M01 = N01*gs[1], M02 = N02*gs[2];
    float M10 = N10*gs[0], M11 = N11*gs[1], M12 = N12*gs[2];
    float M20 = N20*gs[0], M21 = N21*gs[1], M22 = N22*gs[2];
    float c300 = M00*M00 + M01*M01 + M02*M02;
    float c301 = M00*M10 + M01*M11 + M02*M12;
    float c302 = M00*M20 + M01*M21 + M02*M22;
    float c311 = M10*M10 + M11*M11 + M12*M12;
    float c312 = M10*M20 + M11*M21 + M12*M22;
    float c322 = M20*M20 + M21*M21 + M22*M22;

    float X = tx, Y = ty, Z = tz;
    float valid = (Z > 0.2f) ? 1.0f : 0.0f;
    float Zc = fmaxf(Z, 0.2f);
    float mx = FXc*X/Zc + CXc;
    float my = FYc*Y/Zc + CYc;
    float j00 = FXc/Zc;
    float j02 = -FXc*X/(Zc*Zc);
    float j11 = FYc/Zc;
    float j12 = -FYc*Y/(Zc*Zc);

    float u0 = j00*c300 + j02*c302;
    float u1 = j00*c301 + j02*c312;
    float u2 = j00*c302 + j02*c322;
    float v1 = j11*c311 + j12*c312;
    float v2 = j11*c312 + j12*c322;
    float cA = u0*j00 + u2*j02 + 0.3f;
    float cB = u1*j11 + u2*j12;
    float cC = v1*j11 + v2*j12 + 0.3f;
    float det = fmaxf(cA*cC - cB*cB, EPSf);
    float invd = 1.0f/det;

    h1s[f]   = make_float4(mx, my, -0.5f*cC*invd, cB*invd);
    pCs[f]   = -0.5f*cA*invd;
    colds[f] = make_float4(expf(lop[f]) * valid, cols[3*f+0], cols[3*f+1], cols[3*f+2]);

    // stable bitonic sort on (Zc_bits << 32 | idx); Zc > 0 so float bits
    // are order-isomorphic as uint; idx makes it stable (== jnp.argsort).
    int t = f;
    unsigned long long key =
        ((unsigned long long)__float_as_uint(Zc) << 32) | (unsigned int)t;
    __syncthreads();

    #pragma unroll
    for (int k = 2; k <= F_CNT; k <<= 1) {
        bool dir = ((t & k) == 0);
        int j = k >> 1;
        for (; j >= 32; j >>= 1) {
            sk[t] = key;
            __syncthreads();
            unsigned long long other = sk[t ^ j];
            bool takeMin = (dir == ((t & j) == 0));
            key = ((key < other) == takeMin) ? key : other;
            __syncthreads();
        }
        for (; j >= 1; j >>= 1) {
            unsigned long long other = __shfl_xor_sync(0xffffffffu, key, j);
            bool takeMin = (dir == ((t & j) == 0));
            key = ((key < other) == takeMin) ? key : other;
        }
    }

    int s = (int)(key & 0xffffffffu);
    g_sh1[t]   = h1s[s];
    g_spC[t]   = pCs[s];
    g_scold[t] = colds[s];
}

// ============ render: bitmask-culled, 512 thr = 64 slots x 8 segs, 2 px/thread ============
// Block b owns two 64-px row-runs: run = b and run = b+288 (rows differ by 96).
// Per-run 1024-bit candidate mask built by warp ballots; composite loop walks
// set bits only (warp-uniform: warp = one row/run/segment).
__global__ void __launch_bounds__(512, 2) render_kernel(
        float* __restrict__ out,
        const float* __restrict__ img,
        const float* __restrict__ mask)
{
    // sh1 region (16 KB) is re-used as comb[8][128] after the render loop
    __shared__ __align__(16) char smem_raw[16384];
    float4* sh1 = (float4*)smem_raw;                // [1024]
    float4 (*comb)[128] = (float4(*)[128])smem_raw; // [8][128] alias
    __shared__ float  spC[F_CNT];
    __shared__ float4 scold[F_CNT];
    __shared__ unsigned int cmask[2][32];           // per-run candidate bitmask
    __shared__ float  red[128];
    __shared__ int s_last;

    int tid = threadIdx.x;
    #pragma unroll
    for (int i = tid; i < F_CNT; i += 512) {
        sh1[i]   = g_sh1[i];
        spC[i]   = g_spC[i];
        scold[i] = g_scold[i];
    }
    __syncthreads();

    // ---- build candidate masks: 64 word-tasks over 16 warps ----
    {
        int wwid = tid >> 5, lane = tid & 31;
        #pragma unroll
        for (int task = wwid; task < 64; task += 16) {
            int rsel = task >> 5;            // which run (0/1)
            int word = task & 31;
            int g = word * 32 + lane;
            float4 h = sh1[g];
            float pc = spC[g];
            // recover det, cA, cC from the conic: det = 1/(4*pA*pC - pB^2)
            // (det clamp provably never fires: cA,cC >= 0.3 and cov2 is PSD)
            float dv = 1.0f / (4.0f * h.z * pc - h.w * h.w);
            float rx = 6.0f * sqrtf(-2.0f * pc  * dv);   // 6*sqrt(cA)
            float ry = 6.0f * sqrtf(-2.0f * h.z * dv);   // 6*sqrt(cC)
            int run = blockIdx.x + NRBLK * rsel;
            float rowf = (float)(run / 3);
            float x0 = (float)((run % 3) * 64);
            bool pass = (fabsf(rowf - h.y) < ry) &&
                        (h.x + rx >= x0) && (h.x - rx <= x0 + 63.0f);
            unsigned int mm = __ballot_sync(0xffffffffu, pass);
            if (lane == 0) cmask[rsel][word] = mm;
        }
    }
    __syncthreads();

    int pl    = tid & 63;           // pixel slot
    int seg   = tid >> 6;           // depth segment 0..7
    int lane  = pl & 31;
    int chunk = pl >> 5;            // 0/1 -> run select (warp-uniform)
    int run   = blockIdx.x + NRBLK * chunk;
    float fy  = (float)(run / 3);
    float fx0 = (float)((run % 3) * 64 + lane);
    // second pixel: fx1 = fx0 + 32  =>  dx1 = dx0 + 32

    float T0 = 1.0f, r0a = 0.0f, g0a = 0.0f, b0a = 0.0f;
    float T1 = 1.0f, r1a = 0.0f, g1a = 0.0f, b1a = 0.0f;
    #pragma unroll
    for (int w = 0; w < 4; w++) {
        int word = seg * 4 + w;
        unsigned int m = cmask[chunk][word];   // warp-uniform
        int gb = word * 32;
        while (m) {
            int b = __ffs(m) - 1;
            m &= m - 1;
            int i = gb + b;
            float4 h = sh1[i];
            float pc = spC[i];
            float dy = fy - h.y;
            float sB = h.w * dy;                 // pB*dy
            float s2 = (pc * dy) * dy;           // pC*dy^2
            float dx0 = fx0 - h.x;
            float dx1 = dx0 + 32.0f;
            float p0 = fmaf(fmaf(h.z, dx0, sB), dx0, s2);
            float p1 = fmaf(fmaf(h.z, dx1, sB), dx1, s2);
            if (fmaxf(p0, p1) > -18.0f) {        // both alphas < 1.6e-8: skip
                float4 c = scold[i];
                float al0 = fminf(c.x * __expf(fminf(p0, 0.0f)), 0.99f);
                float al1 = fminf(c.x * __expf(fminf(p1, 0.0f)), 0.99f);
                float w0 = al0 * T0, w1 = al1 * T1;
                r0a = fmaf(w0, c.y, r0a);  r1a = fmaf(w1, c.y, r1a);
                g0a = fmaf(w0, c.z, g0a);  g1a = fmaf(w1, c.z, g1a);
                b0a = fmaf(w0, c.w, b0a);  b1a = fmaf(w1, c.w, b1a);
                T0 *= (1.0f - al0);        T1 *= (1.0f - al1);
            }
        }
    }
    __syncthreads();                 // all sh1 reads done before comb aliases it
    comb[seg][pl]      = make_float4(T0, r0a, g0a, b0a);
    comb[seg][pl + 64] = make_float4(T1, r1a, g1a, b1a);
    __syncthreads();

    // ---- per-pixel ordered fold of 8 segments (threads 0..127) ----
    if (tid < 128) {
        float Tt = 1.0f, r = 0.0f, g = 0.0f, b = 0.0f;
#pragma unroll
        for (int s = 0; s < SEG; s++) {
            float4 vv = comb[s][tid];
            r = fmaf(Tt, vv.y, r);
            g = fmaf(Tt, vv.z, g);
            b = fmaf(Tt, vv.w, b);
            Tt *= vv.x;
        }
        float o0 = r + Tt, o1 = g + Tt, o2 = b + Tt;  // 1 - sum(w) == prod(1-alpha)
        // slot = (pl & 63) + 64*half ; px = 64*run + lane + 32*half
        int sl    = tid & 63;
        int half  = tid >> 6;
        int ch    = sl >> 5;
        int ln    = sl & 31;
        int rn    = blockIdx.x + NRBLK * ch;
        int p     = rn * 64 + ln + half * 32;
        out[p]          = o0;
        out[NPIX + p]   = o1;
        out[2*NPIX + p] = o2;

        float m  = mask[p];
        float bt = 1.0f - m;
        float d0 = o0 - fmaf(img[p],          m, bt);
        float d1 = o1 - fmaf(img[NPIX + p],   m, bt);
        float d2 = o2 - fmaf(img[2*NPIX + p], m, bt);
        red[tid] = fmaf(d0, d0, fmaf(d1, d1, d2*d2));
    }
    __syncthreads();
#pragma unroll
    for (int s = 64; s > 0; s >>= 1) {
        if (tid < s) red[tid] += red[tid + s];
        __syncthreads();
    }

    // ---- last block finishes loss (fixed-order => deterministic) + resets state ----
    if (tid == 0) {
        g_partial[blockIdx.x] = red[0];
        __threadfence();
        int ticket = atomicAdd(&g_count, 1);
        s_last = (ticket == NRBLK - 1);
    }
    __syncthreads();
    if (s_last && tid < 32) {
        __threadfence();
        float a = 0.0f;
        for (int i = tid; i < NRBLK; i += 32)
            a += *((volatile float*)&g_partial[i]);
#pragma unroll
        for (int o = 16; o > 0; o >>= 1)
            a += __shfl_down_sync(0xffffffffu, a, o);
        if (tid == 0) {
            out[3 * NPIX] = a / (float)(3 * NPIX);
            g_count = 0;             // reset for next graph replay
        }
    }
}

// ---------------- launch ----------------
extern "C" void kernel_launch(void* const* d_in, const int* in_sizes, int n_in,
                              void* d_out, int out_size)
{
    const float* img   = (const float*)d_in[0];
    const float* mask  = (const float*)d_in[1];
    const float* vp    = (const float*)d_in[2];
    const int*   faces = (const int*)  d_in[3];
    const float* qs    = (const float*)d_in[4];
    const float* ls    = (const float*)d_in[5];
    const float* cols  = (const float*)d_in[6];
    const float* lop   = (const float*)d_in[7];
    float* out = (float*)d_out;

    prep_sort_kernel<<<1, 1024>>>(vp, faces, qs, ls, cols, lop);
    render_kernel<<<NRBLK, 512>>>(out, img, mask);
}

// round 9
// speedup vs baseline: 1.1223x; 1.1223x over previous
#include <cuda_runtime.h>
#include <math.h>

#define F_CNT 1024
#define HH 192
#define WW 192
#define NPIX (HH*WW)
#define FXc 200.0f
#define FYc 200.0f
#define CXc 96.0f
#define CYc 96.0f
#define EPSf 1e-8f
#define SEG 8
#define NRBLK 288                  // render blocks: each owns 2 x 64-px row-runs

// ---------------- device scratch (no allocations allowed) ----------------
__device__ float4 g_sh1[F_CNT];    // sorted: mx, my, pA(=-.5*conA), pB(=-conB)
__device__ float  g_spC[F_CNT];    // sorted: pC(=-.5*conC)
__device__ float4 g_scold[F_CNT];  // sorted: opv, r, g, b
__device__ float  g_partial[NRBLK];
__device__ int    g_count;         // 0-init; ticket counter, reset by last block

// ================= preprocess + stable sort, one block =================
__global__ void __launch_bounds__(1024) prep_sort_kernel(
        const float* __restrict__ vp,
        const int*   __restrict__ faces,
        const float* __restrict__ qs,
        const float* __restrict__ ls,
        const float* __restrict__ cols,
        const float* __restrict__ lop)
{
    __shared__ float4 h1s[F_CNT];
    __shared__ float  pCs[F_CNT];
    __shared__ float4 colds[F_CNT];
    __shared__ unsigned long long sk[F_CNT];

    int f = threadIdx.x;

    int ia = faces[3*f+0], ib = faces[3*f+1], ic = faces[3*f+2];
    float ax = vp[3*ia], ay = vp[3*ia+1], az = vp[3*ia+2];
    float bx = vp[3*ib], by = vp[3*ib+1], bz = vp[3*ib+2];
    float cx = vp[3*ic], cy = vp[3*ic+1], cz = vp[3*ic+2];

    float tx = (ax+bx+cx)/3.0f, ty = (ay+by+cy)/3.0f, tz = (az+bz+cz)/3.0f;

    float e1x = bx-ax, e1y = by-ay, e1z = bz-az;
    float e2x = cx-ax, e2y = cy-ay, e2z = cz-az;
    float l1 = sqrtf(e1x*e1x + e1y*e1y + e1z*e1z);
    float i1 = 1.0f/(l1 + EPSf);
    float xx = e1x*i1, xy = e1y*i1, xz = e1z*i1;
    float nx = e1y*e2z - e1z*e2y;
    float ny = e1z*e2x - e1x*e2z;
    float nz = e1x*e2y - e1y*e2x;
    float ln = sqrtf(nx*nx + ny*ny + nz*nz);
    float in = 1.0f/(ln + EPSf);
    float zx = nx*in, zy = ny*in, zz = nz*in;
    float yx = zy*xz - zz*xy;
    float yy = zz*xx - zx*xz;
    float yz = zx*xy - zy*xx;

    float qw = qs[4*f+0], qx = qs[4*f+1], qy = qs[4*f+2], qz = qs[4*f+3];
    float qn = sqrtf(qw*qw + qx*qx + qy*qy + qz*qz);
    float iq = 1.0f/(qn + EPSf);
    qw *= iq; qx *= iq; qy *= iq; qz *= iq;
    float R00 = 1.0f - 2.0f*(qy*qy + qz*qz), R01 = 2.0f*(qx*qy - qw*qz), R02 = 2.0f*(qx*qz + qw*qy);
    float R10 = 2.0f*(qx*qy + qw*qz), R11 = 1.0f - 2.0f*(qx*qx + qz*qz), R12 = 2.0f*(qy*qz - qw*qx);
    float R20 = 2.0f*(qx*qz - qw*qy), R21 = 2.0f*(qy*qz + qw*qx), R22 = 1.0f - 2.0f*(qx*qx + qy*qy);

    float s0 = expf(ls[3*f+0]), s1 = expf(ls[3*f+1]), s2 = expf(ls[3*f+2]);

    float G[3][3];
    {
        float w0, w1, w2;
        w0 = R00*s0; w1 = R01*s1; w2 = R02*s2;
        G[0][0] = xx*w0 + yx*w1 + zx*w2;
        G[1][0] = xy*w0 + yy*w1 + zy*w2;
        G[2][0] = xz*w0 + yz*w1 + zz*w2;
        w0 = R10*s0; w1 = R11*s1; w2 = R12*s2;
        G[0][1] = xx*w0 + yx*w1 + zx*w2;
        G[1][1] = xy*w0 + yy*w1 + zy*w2;
        G[2][1] = xz*w0 + yz*w1 + zz*w2;
        w0 = R20*s0; w1 = R21*s1; w2 = R22*s2;
        G[0][2] = xx*w0 + yx*w1 + zx*w2;
        G[1][2] = xy*w0 + yy*w1 + zy*w2;
        G[2][2] = xz*w0 + yz*w1 + zz*w2;
    }

    float gs[3], Gr[3][3];
    #pragma unroll
    for (int j = 0; j < 3; j++) {
        gs[j] = sqrtf(G[0][j]*G[0][j] + G[1][j]*G[1][j] + G[2][j]*G[2][j]);
        float ig = 1.0f/(gs[j] + EPSf);
        Gr[0][j] = G[0][j]*ig; Gr[1][j] = G[1][j]*ig; Gr[2][j] = G[2][j]*ig;
    }

    float m00 = Gr[0][0], m11 = Gr[1][1], m22 = Gr[2][2];
    float pw = 0.5f*sqrtf(fmaxf(EPSf, 1.0f + m00 + m11 + m22));
    float px = 0.5f*sqrtf(fmaxf(EPSf, 1.0f + m00 - m11 - m22));
    float py = 0.5f*sqrtf(fmaxf(EPSf, 1.0f - m00 + m11 - m22));
    float pz = 0.5f*sqrtf(fmaxf(EPSf, 1.0f - m00 - m11 + m22));
    px = copysignf(px, Gr[2][1] - Gr[1][2]);
    py = copysignf(py, Gr[0][2] - Gr[2][0]);
    pz = copysignf(pz, Gr[1][0] - Gr[0][1]);

    float pn = sqrtf(pw*pw + px*px + py*py + pz*pz);
    float ip = 1.0f/(pn + EPSf);
    pw *= ip; px *= ip; py *= ip; pz *= ip;
    float N00 = 1.0f - 2.0f*(py*py + pz*pz), N01 = 2.0f*(px*py - pw*pz), N02 = 2.0f*(px*pz + pw*py);
    float N10 = 2.0f*(px*py + pw*pz), N11 = 1.0f - 2.0f*(px*px + pz*pz), N12 = 2.0f*(py*pz - pw*px);
    float N20 = 2.0f*(px*pz - pw*py), N21 = 2.0f*(py*pz + pw*px), N22 = 1.0f - 2.0f*(px*px + py*py);

    float M00 = N00*gs[0], M01 = N01*gs[1], M02 = N02*gs[2];
    float M10 = N10*gs[0], M11 = N11*gs[1], M12 = N12*gs[2];
    float M20 = N20*gs[0], M21 = N21*gs[1], M22 = N22*gs[2];
    float c300 = M00*M00 + M01*M01 + M02*M02;
    float c301 = M00*M10 + M01*M11 + M02*M12;
    float c302 = M00*M20 + M01*M21 + M02*M22;
    float c311 = M10*M10 + M11*M11 + M12*M12;
    float c312 = M10*M20 + M11*M21 + M12*M22;
    float c322 = M20*M20 + M21*M21 + M22*M22;

    float X = tx, Y = ty, Z = tz;
    float valid = (Z > 0.2f) ? 1.0f : 0.0f;
    float Zc = fmaxf(Z, 0.2f);
    float mx = FXc*X/Zc + CXc;
    float my = FYc*Y/Zc + CYc;
    float j00 = FXc/Zc;
    float j02 = -FXc*X/(Zc*Zc);
    float j11 = FYc/Zc;
    float j12 = -FYc*Y/(Zc*Zc);

    float u0 = j00*c300 + j02*c302;
    float u1 = j00*c301 + j02*c312;
    float u2 = j00*c302 + j02*c322;
    float v1 = j11*c311 + j12*c312;
    float v2 = j11*c312 + j12*c322;
    float cA = u0*j00 + u2*j02 + 0.3f;
    float cB = u1*j11 + u2*j12;
    float cC = v1*j11 + v2*j12 + 0.3f;
    float det = fmaxf(cA*cC - cB*cB, EPSf);
    float invd = 1.0f/det;

    h1s[f]   = make_float4(mx, my, -0.5f*cC*invd, cB*invd);
    pCs[f]   = -0.5f*cA*invd;
    colds[f] = make_float4(expf(lop[f]) * valid, cols[3*f+0], cols[3*f+1], cols[3*f+2]);

    // stable bitonic sort on (Zc_bits << 32 | idx); Zc > 0 so float bits
    // are order-isomorphic as uint; idx makes it stable (== jnp.argsort).
    int t = f;
    unsigned long long key =
        ((unsigned long long)__float_as_uint(Zc) << 32) | (unsigned int)t;
    __syncthreads();

    #pragma unroll
    for (int k = 2; k <= F_CNT; k <<= 1) {
        bool dir = ((t & k) == 0);
        int j = k >> 1;
        for (; j >= 32; j >>= 1) {
            sk[t] = key;
            __syncthreads();
            unsigned long long other = sk[t ^ j];
            bool takeMin = (dir == ((t & j) == 0));
            key = ((key < other) == takeMin) ? key : other;
            __syncthreads();
        }
        for (; j >= 1; j >>= 1) {
            unsigned long long other = __shfl_xor_sync(0xffffffffu, key, j);
            bool takeMin = (dir == ((t & j) == 0));
            key = ((key < other) == takeMin) ? key : other;
        }
    }

    int s = (int)(key & 0xffffffffu);
    g_sh1[t]   = h1s[s];
    g_spC[t]   = pCs[s];
    g_scold[t] = colds[s];
}

// ============ render: compacted candidate lists + balanced depth chunks ============
// Block b owns two 64-px row-runs: run = b and run = b+288 (rows differ by 96).
// Per run: ballot-build candidate mask -> order-preserving compaction into a
// u16 list -> 8 depth-segments take equal chunks of the COMPACTED list.
__global__ void __launch_bounds__(512, 2) render_kernel(
        float* __restrict__ out,
        const float* __restrict__ img,
        const float* __restrict__ mask)
{
    // sh1 region (16 KB) is re-used as comb[8][128] after the render loop
    __shared__ __align__(16) char smem_raw[16384];
    float4* sh1 = (float4*)smem_raw;                // [1024]
    float4 (*comb)[128] = (float4(*)[128])smem_raw; // [8][128] alias
    __shared__ float  spC[F_CNT];
    __shared__ float4 scold[F_CNT];
    __shared__ unsigned int cmask[2][32];
    __shared__ int  offs[2][32];
    __shared__ int  total[2];
    __shared__ unsigned short list[2][F_CNT];
    __shared__ float  red[128];
    __shared__ int s_last;

    int tid = threadIdx.x;
    #pragma unroll
    for (int i = tid; i < F_CNT; i += 512) {
        sh1[i]   = g_sh1[i];
        spC[i]   = g_spC[i];
        scold[i] = g_scold[i];
    }
    __syncthreads();

    int wwid = tid >> 5, lane = tid & 31;

    // ---- build candidate masks: 64 word-tasks over 16 warps ----
    #pragma unroll
    for (int task = wwid; task < 64; task += 16) {
        int rsel = task >> 5;            // which run (0/1)
        int word = task & 31;
        int g = word * 32 + lane;
        float4 h = sh1[g];
        float pc = spC[g];
        // recover det, cA, cC from the conic: det = 1/(4*pA*pC - pB^2)
        // (det clamp provably never fires: cA,cC >= 0.3 and cov2 is PSD)
        float dv = 1.0f / (4.0f * h.z * pc - h.w * h.w);
        float rx = 6.0f * sqrtf(-2.0f * pc  * dv);   // 6*sqrt(cA)
        float ry = 6.0f * sqrtf(-2.0f * h.z * dv);   // 6*sqrt(cC)
        int run = blockIdx.x + NRBLK * rsel;
        float rowf = (float)(run / 3);
        float x0 = (float)((run % 3) * 64);
        bool pass = (fabsf(rowf - h.y) < ry) &&
                    (h.x + rx >= x0) && (h.x - rx <= x0 + 63.0f);
        unsigned int mm = __ballot_sync(0xffffffffu, pass);
        if (lane == 0) cmask[rsel][word] = mm;
    }
    __syncthreads();

    // ---- exclusive scan of word popcounts (warps 0,1 -> runs 0,1) ----
    if (tid < 64) {
        int r = tid >> 5, w = tid & 31;
        int c = __popc(cmask[r][w]);
        int incl = c;
        #pragma unroll
        for (int o = 1; o < 32; o <<= 1) {
            int v = __shfl_up_sync(0xffffffffu, incl, o);
            if ((tid & 31) >= o) incl += v;
        }
        offs[r][w] = incl - c;
        if (w == 31) total[r] = incl;
    }
    __syncthreads();

    // ---- write compacted lists (order-preserving) ----
    #pragma unroll
    for (int task = wwid; task < 64; task += 16) {
        int rsel = task >> 5;
        int word = task & 31;
        unsigned int mm = cmask[rsel][word];
        bool pass = (mm >> lane) & 1u;
        if (pass) {
            int rank = __popc(mm & ((1u << lane) - 1u));
            list[rsel][offs[rsel][word] + rank] = (unsigned short)(word * 32 + lane);
        }
    }
    __syncthreads();

    int pl    = tid & 63;           // pixel slot
    int seg   = tid >> 6;           // depth segment 0..7
    int plane = pl & 31;
    int chunk = pl >> 5;            // 0/1 -> run select (warp-uniform)
    int run   = blockIdx.x + NRBLK * chunk;
    float fy  = (float)(run / 3);
    float fx0 = (float)((run % 3) * 64 + plane);
    // second pixel: fx1 = fx0 + 32  =>  dx1 = dx0 + 32

    // balanced depth chunks over the compacted (depth-ordered) list
    int n   = total[chunk];
    int csz = (n + SEG - 1) >> 3;
    int i0  = seg * csz;
    int i1  = min(n, i0 + csz);

    float T0 = 1.0f, r0a = 0.0f, g0a = 0.0f, b0a = 0.0f;
    float T1 = 1.0f, r1a = 0.0f, g1a = 0.0f, b1a = 0.0f;
    #pragma unroll 2
    for (int i = i0; i < i1; i++) {
        int idx = list[chunk][i];
        float4 h = sh1[idx];
        float pc = spC[idx];
        float dy = fy - h.y;
        float sB = h.w * dy;                 // pB*dy
        float s2 = (pc * dy) * dy;           // pC*dy^2
        float dx0 = fx0 - h.x;
        float dx1 = dx0 + 32.0f;
        float p0 = fmaf(fmaf(h.z, dx0, sB), dx0, s2);
        float p1 = fmaf(fmaf(h.z, dx1, sB), dx1, s2);
        if (fmaxf(p0, p1) > -18.0f) {        // both alphas < 1.6e-8: skip
            float4 c = scold[idx];
            float al0 = fminf(c.x * __expf(fminf(p0, 0.0f)), 0.99f);
            float al1 = fminf(c.x * __expf(fminf(p1, 0.0f)), 0.99f);
            float w0 = al0 * T0, w1 = al1 * T1;
            r0a = fmaf(w0, c.y, r0a);  r1a = fmaf(w1, c.y, r1a);
            g0a = fmaf(w0, c.z, g0a);  g1a = fmaf(w1, c.z, g1a);
            b0a = fmaf(w0, c.w, b0a);  b1a = fmaf(w1, c.w, b1a);
            T0 *= (1.0f - al0);        T1 *= (1.0f - al1);
        }
    }
    __syncthreads();                 // all sh1 reads done before comb aliases it
    comb[seg][pl]      = make_float4(T0, r0a, g0a, b0a);
    comb[seg][pl + 64] = make_float4(T1, r1a, g1a, b1a);
    __syncthreads();

    // ---- per-pixel ordered fold of 8 segments (threads 0..127) ----
    if (tid < 128) {
        float Tt = 1.0f, r = 0.0f, g = 0.0f, b = 0.0f;
#pragma unroll
        for (int s = 0; s < SEG; s++) {
            float4 vv = comb[s][tid];
            r = fmaf(Tt, vv.y, r);
            g = fmaf(Tt, vv.z, g);
            b = fmaf(Tt, vv.w, b);
            Tt *= vv.x;
        }
        float o0 = r + Tt, o1 = g + Tt, o2 = b + Tt;  // 1 - sum(w) == prod(1-alpha)
        // slot = (pl & 63) + 64*half ; px = 64*run + lane + 32*half
        int sl    = tid & 63;
        int half  = tid >> 6;
        int ch    = sl >> 5;
        int ln    = sl & 31;
        int rn    = blockIdx.x + NRBLK * ch;
        int p     = rn * 64 + ln + half * 32;
        out[p]          = o0;
        out[NPIX + p]   = o1;
        out[2*NPIX + p] = o2;

        float m  = mask[p];
        float bt = 1.0f - m;
        float d0 = o0 - fmaf(img[p],          m, bt);
        float d1 = o1 - fmaf(img[NPIX + p],   m, bt);
        float d2 = o2 - fmaf(img[2*NPIX + p], m, bt);
        red[tid] = fmaf(d0, d0, fmaf(d1, d1, d2*d2));
    }
    __syncthreads();
#pragma unroll
    for (int s = 64; s > 0; s >>= 1) {
        if (tid < s) red[tid] += red[tid + s];
        __syncthreads();
    }

    // ---- last block finishes loss (fixed-order => deterministic) + resets state ----
    if (tid == 0) {
        g_partial[blockIdx.x] = red[0];
        __threadfence();
        int ticket = atomicAdd(&g_count, 1);
        s_last = (ticket == NRBLK - 1);
    }
    __syncthreads();
    if (s_last && tid < 32) {
        __threadfence();
        float a = 0.0f;
        for (int i = tid; i < NRBLK; i += 32)
            a += *((volatile float*)&g_partial[i]);
#pragma unroll
        for (int o = 16; o > 0; o >>= 1)
            a += __shfl_down_sync(0xffffffffu, a, o);
        if (tid == 0) {
            out[3 * NPIX] = a / (float)(3 * NPIX);
            g_count = 0;             // reset for next graph replay
        }
    }
}

// ---------------- launch ----------------
extern "C" void kernel_launch(void* const* d_in, const int* in_sizes, int n_in,
                              void* d_out, int out_size)
{
    const float* img   = (const float*)d_in[0];
    const float* mask  = (const float*)d_in[1];
    const float* vp    = (const float*)d_in[2];
    const int*   faces = (const int*)  d_in[3];
    const float* qs    = (const float*)d_in[4];
    const float* ls    = (const float*)d_in[5];
    const float* cols  = (const float*)d_in[6];
    const float* lop   = (const float*)d_in[7];
    float* out = (float*)d_out;

    prep_sort_kernel<<<1, 1024>>>(vp, faces, qs, ls, cols, lop);
    render_kernel<<<NRBLK, 512>>>(out, img, mask);
}